// round 8
// baseline (speedup 1.0000x reference)
#include <cuda_runtime.h>
#include <cuda_bf16.h>
#include <cstdint>

// Persistent 4-CTA-cluster LSTM scan, bf16 m16n8k16 HMMA, TWO interleaved
// independent batch groups per cluster (latency hiding across the recurrence).
// T=2048, B=256, E=128, H=256 (4H=1024 gate rows).
//   8 clusters x 4 CTAs = 32 CTAs. Cluster cl owns batch [32cl, 32cl+32):
//   group 0 = first 16 rows, group 1 = next 16. CTA rank r owns hidden units
//   [64r, 64r+64) -> 256 local gate rows (gate-aligned n-tiles, 4 per warp).
//   W recurrent kt 0..9 in registers (80 regs), kt 10..15 + x-part kt 16..23
//   in smem fragments. h exchange: st.async.shared::cluster + mbarrier
//   complete_tx; per group a parity pair of barriers. While group A's pushes
//   are in flight, the SM computes group B's step -> exposed exchange
//   latency ~0. 4 A-fragment buffers (2 groups x 2 parities).

#define T_STEPS 2048
#define BATCH   256
#define EDIM    128
#define HDIM    256
#define CLSZ    4
#define NTHR    256

// smem word map
#define WF_W        0        // W frags: 32nt x 14skt x 32 lanes uint2 = 28672 words
#define AF_W        28672    // A fragments: 4 buffers x 3072 words
#define AF_STRIDE_W 3072
#define MB_W        40960    // 4 mbarriers (G*2+par), 8B each
#define SMEM_WORDS  40968    // 163872 bytes

#define AF_BYTE     (AF_W * 4)
#define MB_BYTE     (MB_W * 4)
#define AF_STRIDE_B (AF_STRIDE_W * 4)
#define TX_BYTES    (CLSZ * NTHR * 8)   // 8192 per group per generation

extern __shared__ uint32_t smem_u[];

__device__ __forceinline__ uint32_t packbf(float lo, float hi) {
    uint32_t u;
    asm("cvt.rn.bf16x2.f32 %0, %1, %2;" : "=r"(u) : "f"(hi), "f"(lo));
    return u;
}
__device__ __forceinline__ float tanha(float x) {
    float y;
    asm("tanh.approx.f32 %0, %1;" : "=f"(y) : "f"(x));
    return y;
}
__device__ __forceinline__ float sigf(float x) { return fmaf(0.5f, tanha(0.5f * x), 0.5f); }
__device__ __forceinline__ void csync() {
    asm volatile("barrier.cluster.arrive.aligned;" ::: "memory");
    asm volatile("barrier.cluster.wait.aligned;" ::: "memory");
}
__device__ __forceinline__ uint32_t smem_u32(const void* p) {
    uint32_t a;
    asm("{ .reg .u64 t; cvta.to.shared.u64 t, %1; cvt.u32.u64 %0, t; }" : "=r"(a) : "l"(p));
    return a;
}
__device__ __forceinline__ uint32_t mapa32(uint32_t a, uint32_t r) {
    uint32_t d;
    asm("mapa.shared::cluster.u32 %0, %1, %2;" : "=r"(d) : "r"(a), "r"(r));
    return d;
}
__device__ __forceinline__ void mbar_init(uint32_t a, uint32_t n) {
    asm volatile("mbarrier.init.shared.b64 [%0], %1;" :: "r"(a), "r"(n) : "memory");
}
__device__ __forceinline__ void mbar_arm(uint32_t a, uint32_t tx) {
    asm volatile("mbarrier.arrive.expect_tx.shared.b64 _, [%0], %1;" :: "r"(a), "r"(tx) : "memory");
}
__device__ __forceinline__ void mbar_wait(uint32_t a, uint32_t phase) {
    uint32_t done;
    asm volatile(
        "{\n\t.reg .pred p;\n\t"
        "mbarrier.try_wait.parity.acquire.cluster.shared::cta.b64 p, [%1], %2;\n\t"
        "selp.b32 %0, 1, 0, p;\n\t}"
        : "=r"(done) : "r"(a), "r"(phase) : "memory");
    if (!done) {
        asm volatile(
            "{\n\t.reg .pred P1;\n\t"
            "W_%=:\n\t"
            "mbarrier.try_wait.parity.acquire.cluster.shared::cta.b64 P1, [%0], %1, 0x989680;\n\t"
            "@P1 bra.uni D_%=;\n\t"
            "bra.uni W_%=;\n\t"
            "D_%=:\n\t}"
            :: "r"(a), "r"(phase) : "memory");
    }
}
__device__ __forceinline__ void st_async64(uint32_t daddr, uint32_t dmbar,
                                           uint32_t lo, uint32_t hi) {
    asm volatile(
        "{\n\t.reg .b64 v;\n\tmov.b64 v, {%2, %3};\n\t"
        "st.async.weak.shared::cluster.mbarrier::complete_tx::bytes.b64 [%0], v, [%1];\n\t}"
        :: "r"(daddr), "r"(dmbar), "r"(lo), "r"(hi) : "memory");
}
__device__ __forceinline__ void mma16816(float d[4], uint32_t a0, uint32_t a1, uint32_t a2,
                                         uint32_t a3, uint32_t b0, uint32_t b1) {
    asm volatile(
        "mma.sync.aligned.m16n8k16.row.col.f32.bf16.bf16.f32 "
        "{%0,%1,%2,%3},{%4,%5,%6,%7},{%8,%9},{%0,%1,%2,%3};"
        : "+f"(d[0]), "+f"(d[1]), "+f"(d[2]), "+f"(d[3])
        : "r"(a0), "r"(a1), "r"(a2), "r"(a3), "r"(b0), "r"(b1));
}
// word offset (within one A buffer) of packed pair holding A[row=b][col,col+1], col even
__device__ __forceinline__ int afrag_word(int b, int col) {
    int kt = col >> 4, kk = col & 15;
    int t3 = (kk >> 1) & 3;
    int r  = ((b >> 3) & 1) | (((kk >> 3) & 1) << 1);
    int ln = (b & 7) * 4 + t3;
    return (kt * 32 + ln) * 4 + r;
}

__global__ void __cluster_dims__(CLSZ, 1, 1) __launch_bounds__(NTHR, 1)
lstm_kernel(const int* __restrict__ inputs, const float* __restrict__ emb,
            const float* __restrict__ Wih, const float* __restrict__ Whh,
            const float* __restrict__ bih, const float* __restrict__ bhh,
            const float* __restrict__ Wout, const float* __restrict__ bout,
            float* __restrict__ out)
{
    const int tid  = threadIdx.x;
    const int lane = tid & 31;
    const int wid  = tid >> 5;
    const int rank = blockIdx.x & (CLSZ - 1);
    const int cl   = blockIdx.x >> 2;
    const int bbase = cl * 32;          // cluster's first batch row

    uint2*    wf = (uint2*)(smem_u + WF_W);
    uint32_t* af = smem_u + AF_W;

    const uint32_t smem_base = smem_u32(smem_u);
    const uint32_t mbL       = smem_base + MB_BYTE;   // local barriers base

    // ---- one-time: smem W frags; skt 0..5 <-> kt 10..15 (h), 6..13 <-> kt 16..23 (x) ----
    for (int idx = tid; idx < 32 * 14 * 32; idx += NTHR) {
        int l   = idx & 31;
        int skt = (idx >> 5) % 14;
        int nt  = idx / (32 * 14);
        int n   = nt * 8 + (l >> 2);
        int R   = ((n >> 6) << 8) + rank * 64 + (n & 63);
        int kt  = (skt < 6) ? (10 + skt) : (16 + skt - 6);
        int ka  = kt * 16 + (l & 3) * 2;
        int kb  = ka + 8;
        float w00 = (ka     < HDIM) ? Whh[R * HDIM + ka]     : Wih[R * EDIM + ka - HDIM];
        float w01 = (ka + 1 < HDIM) ? Whh[R * HDIM + ka + 1] : Wih[R * EDIM + ka + 1 - HDIM];
        float w10 = (kb     < HDIM) ? Whh[R * HDIM + kb]     : Wih[R * EDIM + kb - HDIM];
        float w11 = (kb + 1 < HDIM) ? Whh[R * HDIM + kb + 1] : Wih[R * EDIM + kb + 1 - HDIM];
        wf[idx] = make_uint2(packbf(w00, w01), packbf(w10, w11));
    }

    // ---- one-time: h-part W kt 0..9 -> registers (80 regs) ----
    uint2 wreg[40];
    {
        const int nbase = rank * 64 + wid * 8 + (lane >> 2);
        #pragma unroll
        for (int kt = 0; kt < 10; ++kt) {
            int ka = kt * 16 + (lane & 3) * 2;
            #pragma unroll
            for (int g = 0; g < 4; ++g) {
                int R = (g << 8) + nbase;
                wreg[kt * 4 + g] =
                    make_uint2(packbf(Whh[R * HDIM + ka],     Whh[R * HDIM + ka + 1]),
                               packbf(Whh[R * HDIM + ka + 8], Whh[R * HDIM + ka + 8 + 1]));
            }
        }
    }

    // ---- per-thread cell constants ----
    const int u0 = 8 * wid + ((lane & 3) << 1);
    const int b  = lane >> 2;
    float bias0[4], bias1[4];
    #pragma unroll
    for (int g = 0; g < 4; ++g) {
        int R0 = (g << 8) + rank * 64 + u0;
        bias0[g] = bih[R0] + bhh[R0];
        bias1[g] = bih[R0 + 1] + bhh[R0 + 1];
    }
    const int kcol = rank * 64 + u0;
    const uint32_t pushB = (uint32_t)afrag_word(b, kcol) * 4;  // b and b+8 words adjacent (8B)
    uint32_t remBASE[CLSZ];
    #pragma unroll
    for (uint32_t r = 0; r < CLSZ; ++r) remBASE[r] = mapa32(smem_base, r);

    float cA[4] = {0.f, 0.f, 0.f, 0.f};
    float cB[4] = {0.f, 0.f, 0.f, 0.f};
    float accHA[4][4], accHB[4][4];     // held x-part accumulators per group

    // ---- staging constants ----
    const int sb = tid >> 4;            // batch row within group (0..15)
    const int sp = (tid & 15) * 4;      // col-pair base
    int sword[4];
    #pragma unroll
    for (int s = 0; s < 4; ++s) sword[s] = afrag_word(sb, 256 + 2 * (sp + s));

    // ---- mbarrier init + prologue ----
    if (tid == 0) {
        mbar_init(mbL + 0 * 8, 1);   // G0 par0
        mbar_init(mbL + 1 * 8, 1);   // G0 par1
        mbar_init(mbL + 2 * 8, 1);   // G1 par0
        mbar_init(mbL + 3 * 8, 1);   // G1 par1
        mbar_arm(mbL + 1 * 8, TX_BYTES);   // gen 1, group 0
        mbar_arm(mbL + 3 * 8, TX_BYTES);   // gen 1, group 1
    }
    for (int w = tid; w < 4 * AF_STRIDE_W; w += NTHR) af[w] = 0u;
    __syncthreads();
    // stage x(0) for both groups into their parity-0 buffers
    #pragma unroll
    for (int G = 0; G < 2; ++G) {
        int tok = __ldg(&inputs[bbase + G * 16 + sb]);
        const float4* er = (const float4*)&emb[tok * EDIM + 2 * sp];
        float4 e0 = __ldg(er), e1 = __ldg(er + 1);
        uint32_t* buf = af + (G * 2) * AF_STRIDE_W;
        buf[sword[0]] = packbf(e0.x, e0.y);
        buf[sword[1]] = packbf(e0.z, e0.w);
        buf[sword[2]] = packbf(e1.x, e1.y);
        buf[sword[3]] = packbf(e1.z, e1.w);
    }
    __syncthreads();
    csync();   // all CTAs: barriers armed + buffers staged before any st.async

    // prime held x-part accumulators for t=0
    #pragma unroll
    for (int g = 0; g < 4; ++g)
        #pragma unroll
        for (int j = 0; j < 4; ++j) { accHA[g][j] = 0.f; accHB[g][j] = 0.f; }
    #pragma unroll
    for (int j = 0; j < 8; ++j) {
        uint4 aA = *(const uint4*)(af + 0 * AF_STRIDE_W + ((16 + j) * 32 + lane) * 4);
        uint4 aB = *(const uint4*)(af + 2 * AF_STRIDE_W + ((16 + j) * 32 + lane) * 4);
        #pragma unroll
        for (int g = 0; g < 4; ++g) {
            uint2 bf = wf[((wid + 8 * g) * 14 + 6 + j) * 32 + lane];
            mma16816(accHA[g], aA.x, aA.y, aA.z, aA.w, bf.x, bf.y);
            mma16816(accHB[g], aB.x, aB.y, aB.z, aB.w, bf.x, bf.y);
        }
    }

    uint32_t phA0 = 0, phA1 = 0, phB0 = 0, phB1 = 0;

    // ---- one group-phase of one step ----
    #define PHASE(T_, PAR_, G_, PHW_, ACCH_, CS_)                                          \
    {                                                                                      \
        const int t = (T_);                                                                \
        const uint32_t mbw = mbL + ((G_) * 2 + (PAR_)) * 8;                                \
        if (t > 0) { mbar_wait(mbw, PHW_); PHW_ ^= 1; }                                    \
        if (tid == 0) mbar_arm(mbw, TX_BYTES);        /* re-arm for gen t+2 */             \
        const uint32_t* cur = af + ((G_) * 2 + (PAR_)) * AF_STRIDE_W;                      \
        uint32_t*       nxt = af + ((G_) * 2 + 1 - (PAR_)) * AF_STRIDE_W;                  \
        const bool more = (t + 1 < T_STEPS);                                               \
        float4 e0, e1;                                                                     \
        if (more) {                                                                        \
            int tok = __ldg(&inputs[(t + 1) * BATCH + bbase + (G_) * 16 + sb]);            \
            const float4* er = (const float4*)&emb[tok * EDIM + 2 * sp];                   \
            e0 = __ldg(er); e1 = __ldg(er + 1);                                            \
        }                                                                                  \
        float accW[4][4];                                                                  \
        _Pragma("unroll")                                                                  \
        for (int g = 0; g < 4; ++g) {                                                      \
            accW[g][0] = bias0[g]; accW[g][1] = bias1[g];                                  \
            accW[g][2] = bias0[g]; accW[g][3] = bias1[g];                                  \
        }                                                                                  \
        /* h-part: reg kt 0..4 -> accW, 5..9 -> ACCH_; smem skt 0..2 -> accW, 3..5 -> ACCH_ */ \
        _Pragma("unroll")                                                                  \
        for (int kt = 0; kt < 5; ++kt) {                                                   \
            uint4 a = *(const uint4*)(cur + (kt * 32 + lane) * 4);                         \
            _Pragma("unroll")                                                              \
            for (int g = 0; g < 4; ++g) {                                                  \
                uint2 bf = wreg[kt * 4 + g];                                               \
                mma16816(accW[g], a.x, a.y, a.z, a.w, bf.x, bf.y);                         \
            }                                                                              \
        }                                                                                  \
        _Pragma("unroll")                                                                  \
        for (int kt = 5; kt < 10; ++kt) {                                                  \
            uint4 a = *(const uint4*)(cur + (kt * 32 + lane) * 4);                         \
            _Pragma("unroll")                                                              \
            for (int g = 0; g < 4; ++g) {                                                  \
                uint2 bf = wreg[kt * 4 + g];                                               \
                mma16816(ACCH_[g], a.x, a.y, a.z, a.w, bf.x, bf.y);                        \
            }                                                                              \
        }                                                                                  \
        _Pragma("unroll")                                                                  \
        for (int skt = 0; skt < 6; ++skt) {                                                \
            uint4 a = *(const uint4*)(cur + ((10 + skt) * 32 + lane) * 4);                 \
            _Pragma("unroll")                                                              \
            for (int g = 0; g < 4; ++g) {                                                  \
                uint2 bf = wf[((wid + 8 * g) * 14 + skt) * 32 + lane];                     \
                if (skt < 3) mma16816(accW[g],  a.x, a.y, a.z, a.w, bf.x, bf.y);           \
                else         mma16816(ACCH_[g], a.x, a.y, a.z, a.w, bf.x, bf.y);           \
            }                                                                              \
        }                                                                                  \
        /* cell update in registers */                                                     \
        float s0[4], s1[4], s2[4], s3[4];                                                  \
        _Pragma("unroll")                                                                  \
        for (int g = 0; g < 4; ++g) {                                                      \
            s0[g] = accW[g][0] + ACCH_[g][0];                                              \
            s1[g] = accW[g][1] + ACCH_[g][1];                                              \
            s2[g] = accW[g][2] + ACCH_[g][2];                                              \
            s3[g] = accW[g][3] + ACCH_[g][3];                                              \
        }                                                                                  \
        float i0 = sigf(s0[0]), i1 = sigf(s1[0]), i2 = sigf(s2[0]), i3 = sigf(s3[0]);      \
        float f0 = sigf(s0[1]), f1 = sigf(s1[1]), f2 = sigf(s2[1]), f3 = sigf(s3[1]);      \
        float g0 = tanha(s0[2]), g1 = tanha(s1[2]), g2 = tanha(s2[2]), g3 = tanha(s3[2]);  \
        float o0 = sigf(s0[3]), o1 = sigf(s1[3]), o2 = sigf(s2[3]), o3 = sigf(s3[3]);      \
        CS_[0] = f0 * CS_[0] + i0 * g0;                                                    \
        CS_[1] = f1 * CS_[1] + i1 * g1;                                                    \
        CS_[2] = f2 * CS_[2] + i2 * g2;                                                    \
        CS_[3] = f3 * CS_[3] + i3 * g3;                                                    \
        uint32_t w0 = packbf(o0 * tanha(CS_[0]), o1 * tanha(CS_[1]));                      \
        uint32_t w1 = packbf(o2 * tanha(CS_[2]), o3 * tanha(CS_[3]));                      \
        /* push h(t+1) via st.async; tx completes at dest CTA's group barrier */           \
        const uint32_t afoff = AF_BYTE + ((G_) * 2 + 1 - (PAR_)) * AF_STRIDE_B + pushB;    \
        const uint32_t mboff = MB_BYTE + ((G_) * 2 + 1 - (PAR_)) * 8;                      \
        _Pragma("unroll")                                                                  \
        for (uint32_t r = 0; r < CLSZ; ++r)                                                \
            st_async64(remBASE[r] + afoff, remBASE[r] + mboff, w0, w1);                    \
        /* stage x(t+1) locally */                                                         \
        if (more) {                                                                        \
            nxt[sword[0]] = packbf(e0.x, e0.y);                                            \
            nxt[sword[1]] = packbf(e0.z, e0.w);                                            \
            nxt[sword[2]] = packbf(e1.x, e1.y);                                            \
            nxt[sword[3]] = packbf(e1.z, e1.w);                                            \
        }                                                                                  \
        __syncthreads();                                                                   \
        /* x-part mma for t+1 -> new held accumulator (runs while pushes fly) */           \
        _Pragma("unroll")                                                                  \
        for (int g = 0; g < 4; ++g) {                                                      \
            ACCH_[g][0] = 0.f; ACCH_[g][1] = 0.f; ACCH_[g][2] = 0.f; ACCH_[g][3] = 0.f;    \
        }                                                                                  \
        if (more) {                                                                        \
            _Pragma("unroll")                                                              \
            for (int j = 0; j < 8; ++j) {                                                  \
                uint4 a = *(const uint4*)(nxt + ((16 + j) * 32 + lane) * 4);               \
                _Pragma("unroll")                                                          \
                for (int g = 0; g < 4; ++g) {                                              \
                    uint2 bf = wf[((wid + 8 * g) * 14 + 6 + j) * 32 + lane];               \
                    mma16816(ACCH_[g], a.x, a.y, a.z, a.w, bf.x, bf.y);                    \
                }                                                                          \
            }                                                                              \
        }                                                                                  \
    }

    for (int tt = 0; tt < T_STEPS; tt += 2) {
        PHASE(tt,     0, 0, phA0, accHA, cA)
        PHASE(tt,     0, 1, phB0, accHB, cB)
        PHASE(tt + 1, 1, 0, phA1, accHA, cA)
        PHASE(tt + 1, 1, 1, phB1, accHB, cB)
    }
    #undef PHASE

    // final: gen 2048 (parity 0) for both groups must land before reads
    mbar_wait(mbL + 0 * 8, phA0);
    mbar_wait(mbL + 2 * 8, phB0);

    // ---- head: h_T in each group's parity-0 buffer, fragment layout ----
    if (rank == 0 && tid < 32) {
        const int G  = tid >> 4;
        const int bb = tid & 15;
        const uint32_t* buf = af + (G * 2) * AF_STRIDE_W;
        float s = __ldg(bout);
        float accv = 0.0f;
        #pragma unroll 8
        for (int j = 0; j < HDIM; j += 2) {
            uint32_t u = buf[afrag_word(bb, j)];
            float lo = __uint_as_float(u << 16);
            float hi = __uint_as_float(u & 0xFFFF0000u);
            accv += lo * __ldg(&Wout[j]) + hi * __ldg(&Wout[j + 1]);
        }
        out[bbase + G * 16 + bb] = sigf(s + accv);
    }

    // keep cluster alive until all CTAs received their final pushes
    csync();
}

extern "C" void kernel_launch(void* const* d_in, const int* in_sizes, int n_in,
                              void* d_out, int out_size)
{
    (void)in_sizes; (void)n_in; (void)out_size;
    cudaFuncSetAttribute(lstm_kernel, cudaFuncAttributeMaxDynamicSharedMemorySize,
                         SMEM_WORDS * 4);
    lstm_kernel<<<8 * CLSZ, NTHR, SMEM_WORDS * 4>>>(
        (const int*)d_in[0], (const float*)d_in[1], (const float*)d_in[2],
        (const float*)d_in[3], (const float*)d_in[4], (const float*)d_in[5],
        (const float*)d_in[6], (const float*)d_in[7], (float*)d_out);
}

// round 9
// speedup vs baseline: 1.3438x; 1.3438x over previous
#include <cuda_runtime.h>
#include <cuda_bf16.h>
#include <cstdint>

// Persistent 4-CTA-cluster LSTM scan, bf16 m16n8k16 HMMA, split-K across 16
// warps (512 threads), register W, DSMEM st.async h exchange.
// T=2048, B=256, E=128, H=256 (4H=1024 gate rows).
//   16 clusters x 4 CTAs = 64 CTAs (1/SM). Cluster cl: batch [16cl,16cl+16).
//   CTA rank r: hidden units [64r,64r+64) -> 256 local gate rows.
//   Warp wg=wid&7 owns n-tiles {wg+8g} (gate-aligned). half=wid>>3 splits K:
//     half0: kt 0..7  (W in 64 regs)  -> partial gates, then reduction-read,
//            cell math (c in regs), push h via st.async x4 CTAs
//     half1: kt 8..15 (W in 64 regs) + held x-part acc (kt 16..23, W in smem,
//            computed in the push-flight shadow), writes partials to smem
//   One __syncthreads joins the halves; named barrier 1 orders half1's x
//   staging vs its x-part mma. mbarrier parity pair tracks h generations.

#define T_STEPS 2048
#define BATCH   256
#define EDIM    128
#define HDIM    256
#define CLSZ    4
#define NTHR    512

// smem word map
#define WFX_W       0        // x-part W frags: 32nt x 8skt x 32 lanes uint2 = 16384 words
#define AF_W        16384    // A fragments: 2 buffers x 3072 words
#define AF_STRIDE_W 3072
#define RD_W        22528    // reduction: 16 slots x 256 lanes-ish = 4096 words
#define MB_W        26624    // 2 mbarriers, 8B each
#define SMEM_WORDS  26632    // 106528 bytes

#define AF_BYTE     (AF_W * 4)
#define MB_BYTE     (MB_W * 4)
#define AF_STRIDE_B (AF_STRIDE_W * 4)
#define TX_BYTES    (CLSZ * 256 * 8)   // 4 CTAs x 256 half0 threads x 8B

extern __shared__ uint32_t smem_u[];

__device__ __forceinline__ uint32_t packbf(float lo, float hi) {
    uint32_t u;
    asm("cvt.rn.bf16x2.f32 %0, %1, %2;" : "=r"(u) : "f"(hi), "f"(lo));
    return u;
}
__device__ __forceinline__ float tanha(float x) {
    float y;
    asm("tanh.approx.f32 %0, %1;" : "=f"(y) : "f"(x));
    return y;
}
__device__ __forceinline__ float sigf(float x) { return fmaf(0.5f, tanha(0.5f * x), 0.5f); }
__device__ __forceinline__ void csync() {
    asm volatile("barrier.cluster.arrive.aligned;" ::: "memory");
    asm volatile("barrier.cluster.wait.aligned;" ::: "memory");
}
__device__ __forceinline__ uint32_t smem_u32(const void* p) {
    uint32_t a;
    asm("{ .reg .u64 t; cvta.to.shared.u64 t, %1; cvt.u32.u64 %0, t; }" : "=r"(a) : "l"(p));
    return a;
}
__device__ __forceinline__ uint32_t mapa32(uint32_t a, uint32_t r) {
    uint32_t d;
    asm("mapa.shared::cluster.u32 %0, %1, %2;" : "=r"(d) : "r"(a), "r"(r));
    return d;
}
__device__ __forceinline__ void mbar_init(uint32_t a, uint32_t n) {
    asm volatile("mbarrier.init.shared.b64 [%0], %1;" :: "r"(a), "r"(n) : "memory");
}
__device__ __forceinline__ void mbar_arm(uint32_t a, uint32_t tx) {
    asm volatile("mbarrier.arrive.expect_tx.shared.b64 _, [%0], %1;" :: "r"(a), "r"(tx) : "memory");
}
__device__ __forceinline__ void mbar_wait(uint32_t a, uint32_t phase) {
    uint32_t done;
    asm volatile(
        "{\n\t.reg .pred p;\n\t"
        "mbarrier.try_wait.parity.acquire.cluster.shared::cta.b64 p, [%1], %2;\n\t"
        "selp.b32 %0, 1, 0, p;\n\t}"
        : "=r"(done) : "r"(a), "r"(phase) : "memory");
    if (!done) {
        asm volatile(
            "{\n\t.reg .pred P1;\n\t"
            "W_%=:\n\t"
            "mbarrier.try_wait.parity.acquire.cluster.shared::cta.b64 P1, [%0], %1, 0x989680;\n\t"
            "@P1 bra.uni D_%=;\n\t"
            "bra.uni W_%=;\n\t"
            "D_%=:\n\t}"
            :: "r"(a), "r"(phase) : "memory");
    }
}
__device__ __forceinline__ void st_async64(uint32_t daddr, uint32_t dmbar,
                                           uint32_t lo, uint32_t hi) {
    asm volatile(
        "{\n\t.reg .b64 v;\n\tmov.b64 v, {%2, %3};\n\t"
        "st.async.weak.shared::cluster.mbarrier::complete_tx::bytes.b64 [%0], v, [%1];\n\t}"
        :: "r"(daddr), "r"(dmbar), "r"(lo), "r"(hi) : "memory");
}
__device__ __forceinline__ void mma16816(float d[4], uint32_t a0, uint32_t a1, uint32_t a2,
                                         uint32_t a3, uint32_t b0, uint32_t b1) {
    asm volatile(
        "mma.sync.aligned.m16n8k16.row.col.f32.bf16.bf16.f32 "
        "{%0,%1,%2,%3},{%4,%5,%6,%7},{%8,%9},{%0,%1,%2,%3};"
        : "+f"(d[0]), "+f"(d[1]), "+f"(d[2]), "+f"(d[3])
        : "r"(a0), "r"(a1), "r"(a2), "r"(a3), "r"(b0), "r"(b1));
}
// word offset (within one A buffer) of packed pair holding A[row=b][col,col+1], col even
__device__ __forceinline__ int afrag_word(int b, int col) {
    int kt = col >> 4, kk = col & 15;
    int t3 = (kk >> 1) & 3;
    int r  = ((b >> 3) & 1) | (((kk >> 3) & 1) << 1);
    int ln = (b & 7) * 4 + t3;
    return (kt * 32 + ln) * 4 + r;
}

__global__ void __cluster_dims__(CLSZ, 1, 1) __launch_bounds__(NTHR, 1)
lstm_kernel(const int* __restrict__ inputs, const float* __restrict__ emb,
            const float* __restrict__ Wih, const float* __restrict__ Whh,
            const float* __restrict__ bih, const float* __restrict__ bhh,
            const float* __restrict__ Wout, const float* __restrict__ bout,
            float* __restrict__ out)
{
    const int tid  = threadIdx.x;
    const int lane = tid & 31;
    const int wid  = tid >> 5;
    const int wg   = wid & 7;       // n-tile group (gate-aligned)
    const int half = wid >> 3;      // K split: 0 -> kt 0..7, 1 -> kt 8..15 (+x)
    const int rank = blockIdx.x & (CLSZ - 1);
    const int cl   = blockIdx.x >> 2;

    uint2*    wfx   = (uint2*)(smem_u + WFX_W);
    uint32_t* af    = smem_u + AF_W;
    float*    rdbuf = (float*)(smem_u + RD_W);

    const uint32_t smem_base = smem_u32(smem_u);
    const uint32_t mbL       = smem_base + MB_BYTE;

    // ---- one-time: x-part W (kt 16..23) -> smem fragments ----
    for (int idx = tid; idx < 32 * 8 * 32; idx += NTHR) {
        int l   = idx & 31;
        int skt = (idx >> 5) & 7;
        int nt  = idx >> 8;
        int n   = nt * 8 + (l >> 2);
        int R   = ((n >> 6) << 8) + rank * 64 + (n & 63);
        int ka  = skt * 16 + (l & 3) * 2;          // col within E
        wfx[idx] = make_uint2(packbf(Wih[R * EDIM + ka],     Wih[R * EDIM + ka + 1]),
                              packbf(Wih[R * EDIM + ka + 8], Wih[R * EDIM + ka + 8 + 1]));
    }

    // ---- one-time: h-part W for this half -> registers (64 regs) ----
    uint2 wreg[32];
    {
        const int nbase = rank * 64 + wg * 8 + (lane >> 2);
        const int ktb   = half * 8;
        #pragma unroll
        for (int k = 0; k < 8; ++k) {
            int ka = (ktb + k) * 16 + (lane & 3) * 2;
            #pragma unroll
            for (int g = 0; g < 4; ++g) {
                int R = (g << 8) + nbase;
                wreg[k * 4 + g] =
                    make_uint2(packbf(Whh[R * HDIM + ka],     Whh[R * HDIM + ka + 1]),
                               packbf(Whh[R * HDIM + ka + 8], Whh[R * HDIM + ka + 8 + 1]));
            }
        }
    }

    // ---- per-thread cell constants (half0 does cell math + push) ----
    const int u0 = 8 * wg + ((lane & 3) << 1);
    const int b  = lane >> 2;
    float bias0[4], bias1[4];
    #pragma unroll
    for (int g = 0; g < 4; ++g) {
        int R0 = (g << 8) + rank * 64 + u0;
        bias0[g] = bih[R0] + bhh[R0];
        bias1[g] = bih[R0 + 1] + bhh[R0 + 1];
    }
    const int kcol = rank * 64 + u0;
    const uint32_t pushB = (uint32_t)afrag_word(b, kcol) * 4;
    uint32_t remBASE[CLSZ];
    #pragma unroll
    for (uint32_t r = 0; r < CLSZ; ++r) remBASE[r] = mapa32(smem_base, r);
    float cst[4] = {0.f, 0.f, 0.f, 0.f};

    // reduction slot for this (wg, lane): scalar layout, stride 256 words
    const int rdIdx = wg * 32 + lane;

    // ---- staging constants (half1 stages x): st in 0..255 ----
    const int st = tid & 255;
    const int sb = st >> 4;
    const int sp = (st & 15) * 4;
    int sword[4];
    #pragma unroll
    for (int s = 0; s < 4; ++s) sword[s] = afrag_word(sb, 256 + 2 * (sp + s));

    // ---- mbarrier init + prologue ----
    if (tid == 0) {
        mbar_init(mbL + 0, 1);
        mbar_init(mbL + 8, 1);
        mbar_arm(mbL + 8, TX_BYTES);   // gen 1 -> mb1
    }
    for (int w = tid; w < 2 * AF_STRIDE_W; w += NTHR) af[w] = 0u;
    __syncthreads();
    if (half == 1) {   // stage x(0) into buf0
        int tok = __ldg(&inputs[cl * 16 + sb]);
        const float4* er = (const float4*)&emb[tok * EDIM + 2 * sp];
        float4 e0 = __ldg(er), e1 = __ldg(er + 1);
        af[sword[0]] = packbf(e0.x, e0.y);
        af[sword[1]] = packbf(e0.z, e0.w);
        af[sword[2]] = packbf(e1.x, e1.y);
        af[sword[3]] = packbf(e1.z, e1.w);
    }
    __syncthreads();
    csync();   // barriers armed + buffers staged cluster-wide before any st.async

    // prime held x-part accumulator (half1) for t=0
    float accX[4][4];
    #pragma unroll
    for (int g = 0; g < 4; ++g)
        #pragma unroll
        for (int j = 0; j < 4; ++j) accX[g][j] = 0.f;
    if (half == 1) {
        #pragma unroll
        for (int j = 0; j < 8; ++j) {
            uint4 a = *(const uint4*)(af + ((16 + j) * 32 + lane) * 4);
            #pragma unroll
            for (int g = 0; g < 4; ++g) {
                uint2 bf = wfx[((wg + 8 * g) * 8 + j) * 32 + lane];
                mma16816(accX[g], a.x, a.y, a.z, a.w, bf.x, bf.y);
            }
        }
    }

    uint32_t ph0 = 0, ph1 = 0;

    #define STEP_BODY(T_, PAR_, MBOFF_, PHW_)                                              \
    {                                                                                      \
        const int t = (T_);                                                                \
        const uint32_t mbw = mbL + (MBOFF_);                                               \
        if (t > 0) { mbar_wait(mbw, PHW_); PHW_ ^= 1; }                                    \
        if (tid == 0) mbar_arm(mbw, TX_BYTES);      /* re-arm for gen t+2 */               \
        const uint32_t* cur = af + (PAR_) * AF_STRIDE_W;                                   \
        uint32_t*       nxt = af + (1 - (PAR_)) * AF_STRIDE_W;                             \
        const bool more = (t + 1 < T_STEPS);                                               \
        if (half == 0) {                                                                   \
            /* kt 0..7, split accumulators to halve the HMMA chain */                      \
            float accW[4][4], accV[4][4];                                                  \
            _Pragma("unroll")                                                              \
            for (int g = 0; g < 4; ++g) {                                                  \
                accW[g][0] = bias0[g]; accW[g][1] = bias1[g];                              \
                accW[g][2] = bias0[g]; accW[g][3] = bias1[g];                              \
                accV[g][0] = 0.f; accV[g][1] = 0.f; accV[g][2] = 0.f; accV[g][3] = 0.f;    \
            }                                                                              \
            _Pragma("unroll")                                                              \
            for (int k = 0; k < 4; ++k) {                                                  \
                uint4 a = *(const uint4*)(cur + (k * 32 + lane) * 4);                      \
                _Pragma("unroll")                                                          \
                for (int g = 0; g < 4; ++g) {                                              \
                    uint2 bf = wreg[k * 4 + g];                                            \
                    mma16816(accW[g], a.x, a.y, a.z, a.w, bf.x, bf.y);                     \
                }                                                                          \
            }                                                                              \
            _Pragma("unroll")                                                              \
            for (int k = 4; k < 8; ++k) {                                                  \
                uint4 a = *(const uint4*)(cur + (k * 32 + lane) * 4);                      \
                _Pragma("unroll")                                                          \
                for (int g = 0; g < 4; ++g) {                                              \
                    uint2 bf = wreg[k * 4 + g];                                            \
                    mma16816(accV[g], a.x, a.y, a.z, a.w, bf.x, bf.y);                     \
                }                                                                          \
            }                                                                              \
            __syncthreads();   /* half1 partials now in rdbuf */                           \
            /* join halves, cell math, push */                                             \
            float s0[4], s1[4], s2[4], s3[4];                                              \
            _Pragma("unroll")                                                              \
            for (int g = 0; g < 4; ++g) {                                                  \
                s0[g] = accW[g][0] + accV[g][0] + rdbuf[(g * 4 + 0) * 256 + rdIdx];        \
                s1[g] = accW[g][1] + accV[g][1] + rdbuf[(g * 4 + 1) * 256 + rdIdx];        \
                s2[g] = accW[g][2] + accV[g][2] + rdbuf[(g * 4 + 2) * 256 + rdIdx];        \
                s3[g] = accW[g][3] + accV[g][3] + rdbuf[(g * 4 + 3) * 256 + rdIdx];        \
            }                                                                              \
            float i0 = sigf(s0[0]), i1 = sigf(s1[0]), i2 = sigf(s2[0]), i3 = sigf(s3[0]);  \
            float f0 = sigf(s0[1]), f1 = sigf(s1[1]), f2 = sigf(s2[1]), f3 = sigf(s3[1]);  \
            float g0 = tanha(s0[2]), g1 = tanha(s1[2]), g2 = tanha(s2[2]), g3 = tanha(s3[2]); \
            float o0 = sigf(s0[3]), o1 = sigf(s1[3]), o2 = sigf(s2[3]), o3 = sigf(s3[3]);  \
            cst[0] = f0 * cst[0] + i0 * g0;                                                \
            cst[1] = f1 * cst[1] + i1 * g1;                                                \
            cst[2] = f2 * cst[2] + i2 * g2;                                                \
            cst[3] = f3 * cst[3] + i3 * g3;                                                \
            uint32_t w0 = packbf(o0 * tanha(cst[0]), o1 * tanha(cst[1]));                  \
            uint32_t w1 = packbf(o2 * tanha(cst[2]), o3 * tanha(cst[3]));                  \
            const uint32_t afoff = AF_BYTE + (1 - (PAR_)) * AF_STRIDE_B + pushB;           \
            const uint32_t mboff = MB_BYTE + (8 - (MBOFF_));  /* opposite barrier */       \
            _Pragma("unroll")                                                              \
            for (uint32_t r = 0; r < CLSZ; ++r)                                            \
                st_async64(remBASE[r] + afoff, remBASE[r] + mboff, w0, w1);                \
        } else {                                                                           \
            /* issue emb loads for x(t+1) first (L2 latency hidden by mma) */              \
            float4 e0, e1;                                                                 \
            if (more) {                                                                    \
                int tok = __ldg(&inputs[(t + 1) * BATCH + cl * 16 + sb]);                  \
                const float4* er = (const float4*)&emb[tok * EDIM + 2 * sp];               \
                e0 = __ldg(er); e1 = __ldg(er + 1);                                        \
            }                                                                              \
            /* kt 8..15 into accP; accX holds the x-part -> two half-depth chains */       \
            float accP[4][4];                                                              \
            _Pragma("unroll")                                                              \
            for (int g = 0; g < 4; ++g) {                                                  \
                accP[g][0] = 0.f; accP[g][1] = 0.f; accP[g][2] = 0.f; accP[g][3] = 0.f;    \
            }                                                                              \
            _Pragma("unroll")                                                              \
            for (int k = 0; k < 4; ++k) {                                                  \
                uint4 a = *(const uint4*)(cur + ((8 + k) * 32 + lane) * 4);                \
                _Pragma("unroll")                                                          \
                for (int g = 0; g < 4; ++g) {                                              \
                    uint2 bf = wreg[k * 4 + g];                                            \
                    mma16816(accP[g], a.x, a.y, a.z, a.w, bf.x, bf.y);                     \
                }                                                                          \
            }                                                                              \
            _Pragma("unroll")                                                              \
            for (int k = 4; k < 8; ++k) {                                                  \
                uint4 a = *(const uint4*)(cur + ((8 + k) * 32 + lane) * 4);                \
                _Pragma("unroll")                                                          \
                for (int g = 0; g < 4; ++g) {                                              \
                    uint2 bf = wreg[k * 4 + g];                                            \
                    mma16816(accX[g], a.x, a.y, a.z, a.w, bf.x, bf.y);                     \
                }                                                                          \
            }                                                                              \
            /* write partial sums (conflict-free scalar layout) */                         \
            _Pragma("unroll")                                                              \
            for (int g = 0; g < 4; ++g) {                                                  \
                rdbuf[(g * 4 + 0) * 256 + rdIdx] = accP[g][0] + accX[g][0];                \
                rdbuf[(g * 4 + 1) * 256 + rdIdx] = accP[g][1] + accX[g][1];                \
                rdbuf[(g * 4 + 2) * 256 + rdIdx] = accP[g][2] + accX[g][2];                \
                rdbuf[(g * 4 + 3) * 256 + rdIdx] = accP[g][3] + accX[g][3];                \
            }                                                                              \
            __syncthreads();   /* release partials to half0 */                             \
            /* stage x(t+1); order vs our own x-part mma via named barrier 1 */            \
            if (more) {                                                                    \
                nxt[sword[0]] = packbf(e0.x, e0.y);                                        \
                nxt[sword[1]] = packbf(e0.z, e0.w);                                        \
                nxt[sword[2]] = packbf(e1.x, e1.y);                                        \
                nxt[sword[3]] = packbf(e1.z, e1.w);                                        \
            }                                                                              \
            asm volatile("bar.sync 1, 256;" ::: "memory");                                 \
            /* x-part mma for t+1 -> fresh accX (runs while pushes fly) */                 \
            _Pragma("unroll")                                                              \
            for (int g = 0; g < 4; ++g) {                                                  \
                accX[g][0] = 0.f; accX[g][1] = 0.f; accX[g][2] = 0.f; accX[g][3] = 0.f;    \
            }                                                                              \
            if (more) {                                                                    \
                _Pragma("unroll")                                                          \
                for (int j = 0; j < 8; ++j) {                                              \
                    uint4 a = *(const uint4*)(nxt + ((16 + j) * 32 + lane) * 4);           \
                    _Pragma("unroll")                                                      \
                    for (int g = 0; g < 4; ++g) {                                          \
                        uint2 bf = wfx[((wg + 8 * g) * 8 + j) * 32 + lane];                \
                        mma16816(accX[g], a.x, a.y, a.z, a.w, bf.x, bf.y);                 \
                    }                                                                      \
                }                                                                          \
            }                                                                              \
        }                                                                                  \
    }

    for (int tt = 0; tt < T_STEPS; tt += 2) {
        STEP_BODY(tt,     0, 0, ph0)   // even: wait mb0, push -> mb1
        STEP_BODY(tt + 1, 1, 8, ph1)   // odd:  wait mb1, push -> mb0
    }
    #undef STEP_BODY

    // final: gen 2048 (parity 0) must land in every CTA before reads/exit
    mbar_wait(mbL + 0, ph0);

    // ---- head: h_T in buffer 0, fragment layout, full 256 cols ----
    if (rank == 0 && tid < 16) {
        float s = __ldg(bout);
        int bb = tid;
        float accv = 0.0f;
        #pragma unroll 8
        for (int j = 0; j < HDIM; j += 2) {
            uint32_t u = af[afrag_word(bb, j)];
            float lo = __uint_as_float(u << 16);
            float hi = __uint_as_float(u & 0xFFFF0000u);
            accv += lo * __ldg(&Wout[j]) + hi * __ldg(&Wout[j + 1]);
        }
        out[cl * 16 + bb] = sigf(s + accv);
    }

    // keep cluster alive until all CTAs have received their final pushes
    csync();
}

extern "C" void kernel_launch(void* const* d_in, const int* in_sizes, int n_in,
                              void* d_out, int out_size)
{
    (void)in_sizes; (void)n_in; (void)out_size;
    cudaFuncSetAttribute(lstm_kernel, cudaFuncAttributeMaxDynamicSharedMemorySize,
                         SMEM_WORDS * 4);
    lstm_kernel<<<16 * CLSZ, NTHR, SMEM_WORDS * 4>>>(
        (const int*)d_in[0], (const float*)d_in[1], (const float*)d_in[2],
        (const float*)d_in[3], (const float*)d_in[4], (const float*)d_in[5],
        (const float*)d_in[6], (const float*)d_in[7], (float*)d_out);
}